// round 8
// baseline (speedup 1.0000x reference)
#include <cuda_runtime.h>
#include <cuda_bf16.h>
#include <cstdint>

// LSTM: B=4096, T=2048, I=3, H=32.  out = h_final [B, H] fp32.
// Inputs: x [B,T,I], W_ih [4H,I], W_hh [4H,H], b_ih [4H], b_hh [4H]
//
// Mapping: 1 warp per 3 batch rows (6 independent recurrence chains per SMSP
// at 2 warps/SMSP). lane = hidden index (H==32). W_hh register-resident,
// packed in k-pairs for fma.rn.f32x2; weight registers shared across rows.
// h redistributed via per-warp smem double buffer read as ld.shared.v2.u64
// (8 LDS.128/row, bits land as pre-packed f32x2 operands - zero pack MOVs).
// x via padded smem, one LDS.128 per row-step. x loads software-pipelined.

#define BB 4096
#define TT 2048
#define II 3
#define HH 32
#define RPW 3   // rows per warp
#define WPB 4   // warps per block

typedef unsigned long long u64;

__device__ __forceinline__ u64 pack2(float x, float y) {
    u64 r; asm("mov.b64 %0, {%1, %2};" : "=l"(r) : "f"(x), "f"(y)); return r;
}
__device__ __forceinline__ void unpack2(u64 v, float& a, float& b) {
    asm("mov.b64 {%0, %1}, %2;" : "=f"(a), "=f"(b) : "l"(v));
}
// Blackwell packed dual-fp32 fma: d.lo = a.lo*b.lo + c.lo ; d.hi = a.hi*b.hi + c.hi
__device__ __forceinline__ u64 ffma2(u64 a, u64 b, u64 c) {
    u64 d; asm("fma.rn.f32x2 %0, %1, %2, %3;" : "=l"(d) : "l"(a), "l"(b), "l"(c));
    return d;
}

__device__ __forceinline__ float ex2a(float x) {
    float r; asm("ex2.approx.ftz.f32 %0, %1;" : "=f"(r) : "f"(x)); return r;
}
__device__ __forceinline__ float rcpa(float x) {
    float r; asm("rcp.approx.ftz.f32 %0, %1;" : "=f"(r) : "f"(x)); return r;
}
// sigmoid(x) = 1 / (1 + 2^(-x*log2 e)); safe at both extremes.
__device__ __forceinline__ float sigm(float x) {
    return rcpa(1.0f + ex2a(-1.4426950408889634f * x));
}
// tanh(x) = sign(x) * (1 - e^{-2|x|}) / (1 + e^{-2|x|}); no inf/NaN path.
__device__ __forceinline__ float tanh_f(float x) {
    float ax = fabsf(x);
    float e = ex2a(-2.8853900817779268f * ax);
    float r = (1.0f - e) * rcpa(1.0f + e);
    return copysignf(r, x);
}

// per-row LSTM epilogue: gates -> (h, c) update
__device__ __forceinline__ void epi(u64 aI, u64 aF, u64 aG, u64 aO,
                                    float& h, float& c) {
    float l0, m0, l1, m1, l2, m2, l3, m3;
    unpack2(aI, l0, m0); unpack2(aF, l1, m1);
    unpack2(aG, l2, m2); unpack2(aO, l3, m3);
    float gi = l0 + m0, gf = l1 + m1, gg = l2 + m2, go = l3 + m3;
    float ig = sigm(gi), fg = sigm(gf), gv = tanh_f(gg), og = sigm(go);
    c = fmaf(fg, c, ig * gv);
    h = og * tanh_f(c);
}

__global__ void __launch_bounds__(32 * WPB)
lstm_warp3rows(const float* __restrict__ x,
               const float* __restrict__ W_ih,
               const float* __restrict__ W_hh,
               const float* __restrict__ b_ih,
               const float* __restrict__ b_hh,
               float* __restrict__ out)
{
    // [warp][parity][row][hidden] - 128B row stride, 16B aligned for LDS.128
    __shared__ __align__(16) float hbuf[WPB][2][RPW][HH];
    // [warp][row][step][4]  (x0,x1,x2,0) -> one LDS.128 per row-step
    __shared__ __align__(16) float xbuf[WPB][RPW][32][4];

    const int lane = threadIdx.x & 31;
    const int wib  = threadIdx.x >> 5;
    const int gw   = blockIdx.x * WPB + wib;
    const int b0   = gw * RPW;
    if (b0 >= BB) return;

    // clamp invalid rows to a valid one (loads safe; stores guarded)
    const int r0 = b0;
    const int r1 = (b0 + 1 < BB) ? b0 + 1 : BB - 1;
    const int r2 = (b0 + 2 < BB) ? b0 + 2 : BB - 1;

    const int gi_ = lane, gf_ = lane + 32, gg_ = lane + 64, go_ = lane + 96;

    // ---- W_hh rows into registers, packed along k in pairs (shared by rows) ----
    u64 WI[16], WF[16], WG[16], WO[16];
    {
        const float2* wi = reinterpret_cast<const float2*>(W_hh + gi_ * HH);
        const float2* wf = reinterpret_cast<const float2*>(W_hh + gf_ * HH);
        const float2* wg = reinterpret_cast<const float2*>(W_hh + gg_ * HH);
        const float2* wo = reinterpret_cast<const float2*>(W_hh + go_ * HH);
#pragma unroll
        for (int k = 0; k < 16; ++k) {
            float2 a;
            a = wi[k]; WI[k] = pack2(a.x, a.y);
            a = wf[k]; WF[k] = pack2(a.x, a.y);
            a = wg[k]; WG[k] = pack2(a.x, a.y);
            a = wo[k]; WO[k] = pack2(a.x, a.y);
        }
    }

    // ---- W_ih rows (I=3): packed (w0,w1) and (w2,0) per gate ----
    const u64 XI0 = pack2(W_ih[gi_*II + 0], W_ih[gi_*II + 1]);
    const u64 XI2 = pack2(W_ih[gi_*II + 2], 0.0f);
    const u64 XF0 = pack2(W_ih[gf_*II + 0], W_ih[gf_*II + 1]);
    const u64 XF2 = pack2(W_ih[gf_*II + 2], 0.0f);
    const u64 XG0 = pack2(W_ih[gg_*II + 0], W_ih[gg_*II + 1]);
    const u64 XG2 = pack2(W_ih[gg_*II + 2], 0.0f);
    const u64 XO0 = pack2(W_ih[go_*II + 0], W_ih[go_*II + 1]);
    const u64 XO2 = pack2(W_ih[go_*II + 2], 0.0f);

    // ---- biases (b_ih + b_hh) folded into accumulator init (lo half) ----
    const u64 BI = pack2(b_ih[gi_] + b_hh[gi_], 0.0f);
    const u64 BF = pack2(b_ih[gf_] + b_hh[gf_], 0.0f);
    const u64 BG = pack2(b_ih[gg_] + b_hh[gg_], 0.0f);
    const u64 BO = pack2(b_ih[go_] + b_hh[go_], 0.0f);

    const float* xp0 = x + (size_t)r0 * (TT * II);
    const float* xp1 = x + (size_t)r1 * (TT * II);
    const float* xp2 = x + (size_t)r2 * (TT * II);

    float h0 = 0.f, c0 = 0.f, h1 = 0.f, c1 = 0.f, h2 = 0.f, c2 = 0.f;

    // init h parity-0 buffer with h_{-1} = 0; zero xbuf pad words once
    hbuf[wib][0][0][lane] = 0.0f;
    hbuf[wib][0][1][lane] = 0.0f;
    hbuf[wib][0][2][lane] = 0.0f;
    xbuf[wib][0][lane][3] = 0.0f;
    xbuf[wib][1][lane][3] = 0.0f;
    xbuf[wib][2][lane][3] = 0.0f;

    // ---- prefetch chunk 0 x into registers (coalesced) ----
    float pA0 = xp0[lane], pB0 = xp0[32 + lane], pC0 = xp0[64 + lane];
    float pA1 = xp1[lane], pB1 = xp1[32 + lane], pC1 = xp1[64 + lane];
    float pA2 = xp2[lane], pB2 = xp2[32 + lane], pC2 = xp2[64 + lane];

    // staging remap: flat index j in [0,96) -> (step j/3, comp j%3)
    const int tA = lane / 3,        cA = lane - 3 * tA;
    const int tB = (32 + lane) / 3, cB = (32 + lane) - 3 * tB;
    const int tC = (64 + lane) / 3, cC = (64 + lane) - 3 * tC;

    int p = 0;
    __syncwarp();

    for (int t0 = 0; t0 < TT; t0 += 32) {
        float* xr0 = &xbuf[wib][0][0][0];
        float* xr1 = &xbuf[wib][1][0][0];
        float* xr2 = &xbuf[wib][2][0][0];
        xr0[4*tA + cA] = pA0;  xr0[4*tB + cB] = pB0;  xr0[4*tC + cC] = pC0;
        xr1[4*tA + cA] = pA1;  xr1[4*tB + cB] = pB1;  xr1[4*tC + cC] = pC1;
        xr2[4*tA + cA] = pA2;  xr2[4*tB + cB] = pB2;  xr2[4*tC + cC] = pC2;

        if (t0 + 32 < TT) {
            const float* n0 = xp0 + (t0 + 32) * II;
            const float* n1 = xp1 + (t0 + 32) * II;
            const float* n2 = xp2 + (t0 + 32) * II;
            pA0 = n0[lane]; pB0 = n0[32 + lane]; pC0 = n0[64 + lane];
            pA1 = n1[lane]; pB1 = n1[32 + lane]; pC1 = n1[64 + lane];
            pA2 = n2[lane]; pB2 = n2[32 + lane]; pC2 = n2[64 + lane];
        }
        __syncwarp();

#pragma unroll 2
        for (int s = 0; s < 32; ++s) {
            // x: one LDS.128 per row; .x = packed (x0,x1), .y = (x2, 0)
            ulonglong2 xv0 = *reinterpret_cast<const ulonglong2*>(&xbuf[wib][0][s][0]);
            ulonglong2 xv1 = *reinterpret_cast<const ulonglong2*>(&xbuf[wib][1][s][0]);
            ulonglong2 xv2 = *reinterpret_cast<const ulonglong2*>(&xbuf[wib][2][s][0]);

            u64 aI0 = ffma2(XI0, xv0.x, BI); aI0 = ffma2(XI2, xv0.y, aI0);
            u64 aF0 = ffma2(XF0, xv0.x, BF); aF0 = ffma2(XF2, xv0.y, aF0);
            u64 aG0 = ffma2(XG0, xv0.x, BG); aG0 = ffma2(XG2, xv0.y, aG0);
            u64 aO0 = ffma2(XO0, xv0.x, BO); aO0 = ffma2(XO2, xv0.y, aO0);

            u64 aI1 = ffma2(XI0, xv1.x, BI); aI1 = ffma2(XI2, xv1.y, aI1);
            u64 aF1 = ffma2(XF0, xv1.x, BF); aF1 = ffma2(XF2, xv1.y, aF1);
            u64 aG1 = ffma2(XG0, xv1.x, BG); aG1 = ffma2(XG2, xv1.y, aG1);
            u64 aO1 = ffma2(XO0, xv1.x, BO); aO1 = ffma2(XO2, xv1.y, aO1);

            u64 aI2 = ffma2(XI0, xv2.x, BI); aI2 = ffma2(XI2, xv2.y, aI2);
            u64 aF2 = ffma2(XF0, xv2.x, BF); aF2 = ffma2(XF2, xv2.y, aF2);
            u64 aG2 = ffma2(XG0, xv2.x, BG); aG2 = ffma2(XG2, xv2.y, aG2);
            u64 aO2 = ffma2(XO0, xv2.x, BO); aO2 = ffma2(XO2, xv2.y, aO2);

            const float* hb0 = &hbuf[wib][p][0][0];
            const float* hb1 = &hbuf[wib][p][1][0];
            const float* hb2 = &hbuf[wib][p][2][0];

            // recurrent matvec: 8 LDS.128 per row, bits are pre-packed f32x2 pairs
#pragma unroll
            for (int k = 0; k < 8; ++k) {
                ulonglong2 q0 = *reinterpret_cast<const ulonglong2*>(hb0 + 4 * k);
                ulonglong2 q1 = *reinterpret_cast<const ulonglong2*>(hb1 + 4 * k);
                ulonglong2 q2 = *reinterpret_cast<const ulonglong2*>(hb2 + 4 * k);
                const u64 wA_i = WI[2*k], wB_i = WI[2*k+1];
                const u64 wA_f = WF[2*k], wB_f = WF[2*k+1];
                const u64 wA_g = WG[2*k], wB_g = WG[2*k+1];
                const u64 wA_o = WO[2*k], wB_o = WO[2*k+1];

                aI0 = ffma2(wA_i, q0.x, aI0); aI0 = ffma2(wB_i, q0.y, aI0);
                aF0 = ffma2(wA_f, q0.x, aF0); aF0 = ffma2(wB_f, q0.y, aF0);
                aG0 = ffma2(wA_g, q0.x, aG0); aG0 = ffma2(wB_g, q0.y, aG0);
                aO0 = ffma2(wA_o, q0.x, aO0); aO0 = ffma2(wB_o, q0.y, aO0);

                aI1 = ffma2(wA_i, q1.x, aI1); aI1 = ffma2(wB_i, q1.y, aI1);
                aF1 = ffma2(wA_f, q1.x, aF1); aF1 = ffma2(wB_f, q1.y, aF1);
                aG1 = ffma2(wA_g, q1.x, aG1); aG1 = ffma2(wB_g, q1.y, aG1);
                aO1 = ffma2(wA_o, q1.x, aO1); aO1 = ffma2(wB_o, q1.y, aO1);

                aI2 = ffma2(wA_i, q2.x, aI2); aI2 = ffma2(wB_i, q2.y, aI2);
                aF2 = ffma2(wA_f, q2.x, aF2); aF2 = ffma2(wB_f, q2.y, aF2);
                aG2 = ffma2(wA_g, q2.x, aG2); aG2 = ffma2(wB_g, q2.y, aG2);
                aO2 = ffma2(wA_o, q2.x, aO2); aO2 = ffma2(wB_o, q2.y, aO2);
            }

            epi(aI0, aF0, aG0, aO0, h0, c0);
            epi(aI1, aF1, aG1, aO1, h1, c1);
            epi(aI2, aF2, aG2, aO2, h2, c2);

            // publish h for next step into the other parity buffer
            hbuf[wib][p ^ 1][0][lane] = h0;
            hbuf[wib][p ^ 1][1][lane] = h1;
            hbuf[wib][p ^ 1][2][lane] = h2;
            __syncwarp();
            p ^= 1;
        }
    }

    out[r0 * HH + lane] = h0;
    if (b0 + 1 < BB) out[r1 * HH + lane] = h1;
    if (b0 + 2 < BB) out[r2 * HH + lane] = h2;
}

extern "C" void kernel_launch(void* const* d_in, const int* in_sizes, int n_in,
                              void* d_out, int out_size) {
    const float* x    = (const float*)d_in[0];
    const float* W_ih = (const float*)d_in[1];
    const float* W_hh = (const float*)d_in[2];
    const float* b_ih = (const float*)d_in[3];
    const float* b_hh = (const float*)d_in[4];
    float* out = (float*)d_out;

    // 3 rows per warp: ceil(4096/3)=1366 warps -> 342 blocks of 4 warps
    const int n_warps  = (BB + RPW - 1) / RPW;
    const int n_blocks = (n_warps + WPB - 1) / WPB;
    dim3 block(32 * WPB);
    dim3 grid(n_blocks);
    lstm_warp3rows<<<grid, block>>>(x, W_ih, W_hh, b_ih, b_hh, out);
}

// round 10
// speedup vs baseline: 1.1015x; 1.1015x over previous
#include <cuda_runtime.h>
#include <cuda_bf16.h>
#include <cstdint>

// LSTM: B=4096, T=2048, I=3, H=32.  out = h_final [B, H] fp32.
// Inputs: x [B,T,I], W_ih [4H,I], W_hh [4H,H], b_ih [4H], b_hh [4H]
//
// Mapping: 1 warp per 4 batch rows -> 1024 warps, 256 blocks of 4 warps:
// fits the chip in ONE wave (<=296 resident blocks at 2 blocks/SM), removing
// the 2-wave makespan penalty that masked the RPW=3 ILP win (R8 post-mortem:
// per-row cost 535 -> 366 us going 2->3 rows, but makespan stayed 2*T_block).
// lane = hidden index (H==32). W_hh register-resident, packed in k-pairs for
// fma.rn.f32x2; weight registers shared across all 4 rows. h redistributed via
// per-warp smem double buffer read as ld.shared.v2.u64 (pre-packed f32x2
// operands, zero pack MOVs). x via padded smem, one LDS.128 per row-step,
// software-pipelined gmem staging.

#define BB 4096
#define TT 2048
#define II 3
#define HH 32
#define RPW 4   // rows per warp (4096 = 1024 warps * 4 exactly - no tail)
#define WPB 4   // warps per block -> grid = 256 blocks (single wave)

typedef unsigned long long u64;

__device__ __forceinline__ u64 pack2(float x, float y) {
    u64 r; asm("mov.b64 %0, {%1, %2};" : "=l"(r) : "f"(x), "f"(y)); return r;
}
__device__ __forceinline__ void unpack2(u64 v, float& a, float& b) {
    asm("mov.b64 {%0, %1}, %2;" : "=f"(a), "=f"(b) : "l"(v));
}
// Blackwell packed dual-fp32 fma: d.lo = a.lo*b.lo + c.lo ; d.hi = a.hi*b.hi + c.hi
__device__ __forceinline__ u64 ffma2(u64 a, u64 b, u64 c) {
    u64 d; asm("fma.rn.f32x2 %0, %1, %2, %3;" : "=l"(d) : "l"(a), "l"(b), "l"(c));
    return d;
}

__device__ __forceinline__ float ex2a(float x) {
    float r; asm("ex2.approx.ftz.f32 %0, %1;" : "=f"(r) : "f"(x)); return r;
}
__device__ __forceinline__ float rcpa(float x) {
    float r; asm("rcp.approx.ftz.f32 %0, %1;" : "=f"(r) : "f"(x)); return r;
}
// sigmoid(x) = 1 / (1 + 2^(-x*log2 e)); safe at both extremes.
__device__ __forceinline__ float sigm(float x) {
    return rcpa(1.0f + ex2a(-1.4426950408889634f * x));
}
// tanh(x) = sign(x) * (1 - e^{-2|x|}) / (1 + e^{-2|x|}); no inf/NaN path.
__device__ __forceinline__ float tanh_f(float x) {
    float ax = fabsf(x);
    float e = ex2a(-2.8853900817779268f * ax);
    float r = (1.0f - e) * rcpa(1.0f + e);
    return copysignf(r, x);
}

// per-row LSTM epilogue: gates -> (h, c) update
__device__ __forceinline__ void epi(u64 aI, u64 aF, u64 aG, u64 aO,
                                    float& h, float& c) {
    float l0, m0, l1, m1, l2, m2, l3, m3;
    unpack2(aI, l0, m0); unpack2(aF, l1, m1);
    unpack2(aG, l2, m2); unpack2(aO, l3, m3);
    float gi = l0 + m0, gf = l1 + m1, gg = l2 + m2, go = l3 + m3;
    float ig = sigm(gi), fg = sigm(gf), gv = tanh_f(gg), og = sigm(go);
    c = fmaf(fg, c, ig * gv);
    h = og * tanh_f(c);
}

__global__ void __launch_bounds__(32 * WPB)
lstm_warp4rows(const float* __restrict__ x,
               const float* __restrict__ W_ih,
               const float* __restrict__ W_hh,
               const float* __restrict__ b_ih,
               const float* __restrict__ b_hh,
               float* __restrict__ out)
{
    // [warp][parity][row][hidden] - 128B row stride, 16B aligned for LDS.128
    __shared__ __align__(16) float hbuf[WPB][2][RPW][HH];
    // [warp][row][step][4]  (x0,x1,x2,0) -> one LDS.128 per row-step
    __shared__ __align__(16) float xbuf[WPB][RPW][32][4];

    const int lane = threadIdx.x & 31;
    const int wib  = threadIdx.x >> 5;
    const int gw   = blockIdx.x * WPB + wib;
    const int b0   = gw * RPW;   // always < BB: 256*4 warps * 4 rows = 4096 exact

    const int gi_ = lane, gf_ = lane + 32, gg_ = lane + 64, go_ = lane + 96;

    // ---- W_hh rows into registers, packed along k in pairs (shared by rows) ----
    u64 WI[16], WF[16], WG[16], WO[16];
    {
        const float2* wi = reinterpret_cast<const float2*>(W_hh + gi_ * HH);
        const float2* wf = reinterpret_cast<const float2*>(W_hh + gf_ * HH);
        const float2* wg = reinterpret_cast<const float2*>(W_hh + gg_ * HH);
        const float2* wo = reinterpret_cast<const float2*>(W_hh + go_ * HH);
#pragma unroll
        for (int k = 0; k < 16; ++k) {
            float2 a;
            a = wi[k]; WI[k] = pack2(a.x, a.y);
            a = wf[k]; WF[k] = pack2(a.x, a.y);
            a = wg[k]; WG[k] = pack2(a.x, a.y);
            a = wo[k]; WO[k] = pack2(a.x, a.y);
        }
    }

    // ---- W_ih rows (I=3): packed (w0,w1) and (w2,0) per gate ----
    const u64 XI0 = pack2(W_ih[gi_*II + 0], W_ih[gi_*II + 1]);
    const u64 XI2 = pack2(W_ih[gi_*II + 2], 0.0f);
    const u64 XF0 = pack2(W_ih[gf_*II + 0], W_ih[gf_*II + 1]);
    const u64 XF2 = pack2(W_ih[gf_*II + 2], 0.0f);
    const u64 XG0 = pack2(W_ih[gg_*II + 0], W_ih[gg_*II + 1]);
    const u64 XG2 = pack2(W_ih[gg_*II + 2], 0.0f);
    const u64 XO0 = pack2(W_ih[go_*II + 0], W_ih[go_*II + 1]);
    const u64 XO2 = pack2(W_ih[go_*II + 2], 0.0f);

    // ---- biases (b_ih + b_hh) folded into accumulator init (lo half) ----
    const u64 BI = pack2(b_ih[gi_] + b_hh[gi_], 0.0f);
    const u64 BF = pack2(b_ih[gf_] + b_hh[gf_], 0.0f);
    const u64 BG = pack2(b_ih[gg_] + b_hh[gg_], 0.0f);
    const u64 BO = pack2(b_ih[go_] + b_hh[go_], 0.0f);

    const float* xp[RPW];
#pragma unroll
    for (int r = 0; r < RPW; ++r)
        xp[r] = x + (size_t)(b0 + r) * (TT * II);

    float h[RPW], c[RPW];
#pragma unroll
    for (int r = 0; r < RPW; ++r) { h[r] = 0.0f; c[r] = 0.0f; }

    // init h parity-0 buffer with h_{-1} = 0; zero xbuf pad words once
#pragma unroll
    for (int r = 0; r < RPW; ++r) {
        hbuf[wib][0][r][lane] = 0.0f;
        xbuf[wib][r][lane][3] = 0.0f;
    }

    // ---- prefetch chunk 0 x into registers (coalesced) ----
    float pA[RPW], pB[RPW], pC[RPW];
#pragma unroll
    for (int r = 0; r < RPW; ++r) {
        pA[r] = xp[r][lane];
        pB[r] = xp[r][32 + lane];
        pC[r] = xp[r][64 + lane];
    }

    // staging remap: flat index j in [0,96) -> (step j/3, comp j%3)
    const int tA = lane / 3,        cA = lane - 3 * tA;
    const int tB = (32 + lane) / 3, cB = (32 + lane) - 3 * tB;
    const int tC = (64 + lane) / 3, cC = (64 + lane) - 3 * tC;

    int p = 0;
    __syncwarp();

    for (int t0 = 0; t0 < TT; t0 += 32) {
        // stage current chunk's x into smem (remapped to 4-float stride)
#pragma unroll
        for (int r = 0; r < RPW; ++r) {
            float* xr = &xbuf[wib][r][0][0];
            xr[4*tA + cA] = pA[r];
            xr[4*tB + cB] = pB[r];
            xr[4*tC + cC] = pC[r];
        }

        // prefetch next chunk (hides DRAM latency under 32 inner steps)
        if (t0 + 32 < TT) {
#pragma unroll
            for (int r = 0; r < RPW; ++r) {
                const float* xn = xp[r] + (t0 + 32) * II;
                pA[r] = xn[lane];
                pB[r] = xn[32 + lane];
                pC[r] = xn[64 + lane];
            }
        }
        __syncwarp();

#pragma unroll 2
        for (int s = 0; s < 32; ++s) {
            u64 aI[RPW], aF[RPW], aG[RPW], aO[RPW];

            // x: one LDS.128 per row; .x = packed (x0,x1), .y = (x2, 0)
#pragma unroll
            for (int r = 0; r < RPW; ++r) {
                ulonglong2 xv = *reinterpret_cast<const ulonglong2*>(&xbuf[wib][r][s][0]);
                aI[r] = ffma2(XI0, xv.x, BI); aI[r] = ffma2(XI2, xv.y, aI[r]);
                aF[r] = ffma2(XF0, xv.x, BF); aF[r] = ffma2(XF2, xv.y, aF[r]);
                aG[r] = ffma2(XG0, xv.x, BG); aG[r] = ffma2(XG2, xv.y, aG[r]);
                aO[r] = ffma2(XO0, xv.x, BO); aO[r] = ffma2(XO2, xv.y, aO[r]);
            }

            // recurrent matvec: 8 LDS.128 per row, bits are pre-packed f32x2 pairs
#pragma unroll
            for (int k = 0; k < 8; ++k) {
                const u64 wA_i = WI[2*k], wB_i = WI[2*k+1];
                const u64 wA_f = WF[2*k], wB_f = WF[2*k+1];
                const u64 wA_g = WG[2*k], wB_g = WG[2*k+1];
                const u64 wA_o = WO[2*k], wB_o = WO[2*k+1];
#pragma unroll
                for (int r = 0; r < RPW; ++r) {
                    ulonglong2 q = *reinterpret_cast<const ulonglong2*>(
                        &hbuf[wib][p][r][0] + 4 * k);
                    aI[r] = ffma2(wA_i, q.x, aI[r]); aI[r] = ffma2(wB_i, q.y, aI[r]);
                    aF[r] = ffma2(wA_f, q.x, aF[r]); aF[r] = ffma2(wB_f, q.y, aF[r]);
                    aG[r] = ffma2(wA_g, q.x, aG[r]); aG[r] = ffma2(wB_g, q.y, aG[r]);
                    aO[r] = ffma2(wA_o, q.x, aO[r]); aO[r] = ffma2(wB_o, q.y, aO[r]);
                }
            }

#pragma unroll
            for (int r = 0; r < RPW; ++r)
                epi(aI[r], aF[r], aG[r], aO[r], h[r], c[r]);

            // publish h for next step into the other parity buffer
#pragma unroll
            for (int r = 0; r < RPW; ++r)
                hbuf[wib][p ^ 1][r][lane] = h[r];
            __syncwarp();
            p ^= 1;
        }
    }

#pragma unroll
    for (int r = 0; r < RPW; ++r)
        out[(b0 + r) * HH + lane] = h[r];
}

extern "C" void kernel_launch(void* const* d_in, const int* in_sizes, int n_in,
                              void* d_out, int out_size) {
    const float* x    = (const float*)d_in[0];
    const float* W_ih = (const float*)d_in[1];
    const float* W_hh = (const float*)d_in[2];
    const float* b_ih = (const float*)d_in[3];
    const float* b_hh = (const float*)d_in[4];
    float* out = (float*)d_out;

    // 4 rows per warp: 1024 warps -> 256 blocks of 4 warps (single wave)
    dim3 block(32 * WPB);
    dim3 grid(BB / (RPW * WPB));
    lstm_warp4rows<<<grid, block>>>(x, W_ih, W_hh, b_ih, b_hh, out);
}

// round 11
// speedup vs baseline: 1.2358x; 1.1219x over previous
#include <cuda_runtime.h>
#include <cuda_bf16.h>
#include <cstdint>

// LSTM: B=4096, T=2048, I=3, H=32.  out = h_final [B, H] fp32.
// Inputs: x [B,T,I], W_ih [4H,I], W_hh [4H,H], b_ih [4H], b_hh [4H]
//
// Balanced single-wave mapping (R10 post-mortem: 256 blocks -> 108 SMs with
// 8 rows/SMSP, 40 SMs with 4 -> makespan bound by 8):
//   1184 warps = 296 blocks x 4 warps = exactly 2 blocks per SM (one wave).
//   Blocks 0..135: each warp handles 4 rows (544 warps x 4 = 2176 rows).
//   Blocks 136..295: each warp handles 3 rows (640 warps x 3 = 1920 rows).
//   Classic placement maps bid%148 -> SM, so SM s pairs block s with s+148:
//   4-row + 3-row = 7 rows/SMSP (s<136), 3+3 = 6 (s>=136). Max load 8 -> 7.
// Per-warp machinery unchanged: W_hh register-resident packed for fma.rn.f32x2
// (weights shared across rows), h via per-warp smem parity buffer read as
// LDS.128 pre-packed pairs, x via padded smem, pipelined gmem staging.

#define BB 4096
#define TT 2048
#define II 3
#define HH 32
#define RPWMAX 4
#define WPB 4            // warps per block
#define NBLK4 136        // blocks whose warps take 4 rows
#define NWARP4 (NBLK4 * WPB)       // 544
#define ROWS4 (NWARP4 * 4)         // 2176
#define GRID (148 * 2)             // 296 blocks = 1184 warps, 2 blocks/SM

typedef unsigned long long u64;

__device__ __forceinline__ u64 pack2(float x, float y) {
    u64 r; asm("mov.b64 %0, {%1, %2};" : "=l"(r) : "f"(x), "f"(y)); return r;
}
__device__ __forceinline__ void unpack2(u64 v, float& a, float& b) {
    asm("mov.b64 {%0, %1}, %2;" : "=f"(a), "=f"(b) : "l"(v));
}
// Blackwell packed dual-fp32 fma: d.lo = a.lo*b.lo + c.lo ; d.hi = a.hi*b.hi + c.hi
__device__ __forceinline__ u64 ffma2(u64 a, u64 b, u64 c) {
    u64 d; asm("fma.rn.f32x2 %0, %1, %2, %3;" : "=l"(d) : "l"(a), "l"(b), "l"(c));
    return d;
}

__device__ __forceinline__ float ex2a(float x) {
    float r; asm("ex2.approx.ftz.f32 %0, %1;" : "=f"(r) : "f"(x)); return r;
}
__device__ __forceinline__ float rcpa(float x) {
    float r; asm("rcp.approx.ftz.f32 %0, %1;" : "=f"(r) : "f"(x)); return r;
}
// sigmoid(x) = 1 / (1 + 2^(-x*log2 e)); safe at both extremes.
__device__ __forceinline__ float sigm(float x) {
    return rcpa(1.0f + ex2a(-1.4426950408889634f * x));
}
// tanh(x) = sign(x) * (1 - e^{-2|x|}) / (1 + e^{-2|x|}); no inf/NaN path.
__device__ __forceinline__ float tanh_f(float x) {
    float ax = fabsf(x);
    float e = ex2a(-2.8853900817779268f * ax);
    float r = (1.0f - e) * rcpa(1.0f + e);
    return copysignf(r, x);
}

// per-row LSTM epilogue: gates -> (h, c) update
__device__ __forceinline__ void epi(u64 aI, u64 aF, u64 aG, u64 aO,
                                    float& h, float& c) {
    float l0, m0, l1, m1, l2, m2, l3, m3;
    unpack2(aI, l0, m0); unpack2(aF, l1, m1);
    unpack2(aG, l2, m2); unpack2(aO, l3, m3);
    float gi = l0 + m0, gf = l1 + m1, gg = l2 + m2, go = l3 + m3;
    float ig = sigm(gi), fg = sigm(gf), gv = tanh_f(gg), og = sigm(go);
    c = fmaf(fg, c, ig * gv);
    h = og * tanh_f(c);
}

// The full per-warp LSTM over R batch rows. R is compile-time (3 or 4).
template<int R>
__device__ __forceinline__ void lstm_body(
    int lane, int wib, int b0,
    const float* __restrict__ x,
    const float* __restrict__ W_ih,
    const float* __restrict__ W_hh,
    const float* __restrict__ b_ih,
    const float* __restrict__ b_hh,
    float* __restrict__ out,
    float (&hbuf)[WPB][2][RPWMAX][HH],
    float (&xbuf)[WPB][RPWMAX][32][4])
{
    const int gi_ = lane, gf_ = lane + 32, gg_ = lane + 64, go_ = lane + 96;

    // ---- W_hh rows into registers, packed along k in pairs (shared by rows) ----
    u64 WI[16], WF[16], WG[16], WO[16];
    {
        const float2* wi = reinterpret_cast<const float2*>(W_hh + gi_ * HH);
        const float2* wf = reinterpret_cast<const float2*>(W_hh + gf_ * HH);
        const float2* wg = reinterpret_cast<const float2*>(W_hh + gg_ * HH);
        const float2* wo = reinterpret_cast<const float2*>(W_hh + go_ * HH);
#pragma unroll
        for (int k = 0; k < 16; ++k) {
            float2 a;
            a = wi[k]; WI[k] = pack2(a.x, a.y);
            a = wf[k]; WF[k] = pack2(a.x, a.y);
            a = wg[k]; WG[k] = pack2(a.x, a.y);
            a = wo[k]; WO[k] = pack2(a.x, a.y);
        }
    }

    // ---- W_ih rows (I=3): packed (w0,w1) and (w2,0) per gate ----
    const u64 XI0 = pack2(W_ih[gi_*II + 0], W_ih[gi_*II + 1]);
    const u64 XI2 = pack2(W_ih[gi_*II + 2], 0.0f);
    const u64 XF0 = pack2(W_ih[gf_*II + 0], W_ih[gf_*II + 1]);
    const u64 XF2 = pack2(W_ih[gf_*II + 2], 0.0f);
    const u64 XG0 = pack2(W_ih[gg_*II + 0], W_ih[gg_*II + 1]);
    const u64 XG2 = pack2(W_ih[gg_*II + 2], 0.0f);
    const u64 XO0 = pack2(W_ih[go_*II + 0], W_ih[go_*II + 1]);
    const u64 XO2 = pack2(W_ih[go_*II + 2], 0.0f);

    // ---- biases (b_ih + b_hh) folded into accumulator init (lo half) ----
    const u64 BI = pack2(b_ih[gi_] + b_hh[gi_], 0.0f);
    const u64 BF = pack2(b_ih[gf_] + b_hh[gf_], 0.0f);
    const u64 BG = pack2(b_ih[gg_] + b_hh[gg_], 0.0f);
    const u64 BO = pack2(b_ih[go_] + b_hh[go_], 0.0f);

    const float* xp[R];
#pragma unroll
    for (int r = 0; r < R; ++r)
        xp[r] = x + (size_t)(b0 + r) * (TT * II);

    float h[R], c[R];
#pragma unroll
    for (int r = 0; r < R; ++r) { h[r] = 0.0f; c[r] = 0.0f; }

    // init h parity-0 buffer with h_{-1} = 0; zero xbuf pad words once
#pragma unroll
    for (int r = 0; r < R; ++r) {
        hbuf[wib][0][r][lane] = 0.0f;
        xbuf[wib][r][lane][3] = 0.0f;
    }

    // ---- prefetch chunk 0 x into registers (coalesced) ----
    float pA[R], pB[R], pC[R];
#pragma unroll
    for (int r = 0; r < R; ++r) {
        pA[r] = xp[r][lane];
        pB[r] = xp[r][32 + lane];
        pC[r] = xp[r][64 + lane];
    }

    // staging remap: flat index j in [0,96) -> (step j/3, comp j%3)
    const int tA = lane / 3,        cA = lane - 3 * tA;
    const int tB = (32 + lane) / 3, cB = (32 + lane) - 3 * tB;
    const int tC = (64 + lane) / 3, cC = (64 + lane) - 3 * tC;

    int p = 0;
    __syncwarp();

    for (int t0 = 0; t0 < TT; t0 += 32) {
        // stage current chunk's x into smem (remapped to 4-float stride)
#pragma unroll
        for (int r = 0; r < R; ++r) {
            float* xr = &xbuf[wib][r][0][0];
            xr[4*tA + cA] = pA[r];
            xr[4*tB + cB] = pB[r];
            xr[4*tC + cC] = pC[r];
        }

        // prefetch next chunk (hides DRAM latency under 32 inner steps)
        if (t0 + 32 < TT) {
#pragma unroll
            for (int r = 0; r < R; ++r) {
                const float* xn = xp[r] + (t0 + 32) * II;
                pA[r] = xn[lane];
                pB[r] = xn[32 + lane];
                pC[r] = xn[64 + lane];
            }
        }
        __syncwarp();

#pragma unroll 2
        for (int s = 0; s < 32; ++s) {
            u64 aI[R], aF[R], aG[R], aO[R];

            // x: one LDS.128 per row; .x = packed (x0,x1), .y = (x2, 0)
#pragma unroll
            for (int r = 0; r < R; ++r) {
                ulonglong2 xv = *reinterpret_cast<const ulonglong2*>(&xbuf[wib][r][s][0]);
                aI[r] = ffma2(XI0, xv.x, BI); aI[r] = ffma2(XI2, xv.y, aI[r]);
                aF[r] = ffma2(XF0, xv.x, BF); aF[r] = ffma2(XF2, xv.y, aF[r]);
                aG[r] = ffma2(XG0, xv.x, BG); aG[r] = ffma2(XG2, xv.y, aG[r]);
                aO[r] = ffma2(XO0, xv.x, BO); aO[r] = ffma2(XO2, xv.y, aO[r]);
            }

            // recurrent matvec: 8 LDS.128 per row, bits are pre-packed f32x2 pairs
#pragma unroll
            for (int k = 0; k < 8; ++k) {
                const u64 wA_i = WI[2*k], wB_i = WI[2*k+1];
                const u64 wA_f = WF[2*k], wB_f = WF[2*k+1];
                const u64 wA_g = WG[2*k], wB_g = WG[2*k+1];
                const u64 wA_o = WO[2*k], wB_o = WO[2*k+1];
#pragma unroll
                for (int r = 0; r < R; ++r) {
                    ulonglong2 q = *reinterpret_cast<const ulonglong2*>(
                        &hbuf[wib][p][r][0] + 4 * k);
                    aI[r] = ffma2(wA_i, q.x, aI[r]); aI[r] = ffma2(wB_i, q.y, aI[r]);
                    aF[r] = ffma2(wA_f, q.x, aF[r]); aF[r] = ffma2(wB_f, q.y, aF[r]);
                    aG[r] = ffma2(wA_g, q.x, aG[r]); aG[r] = ffma2(wB_g, q.y, aG[r]);
                    aO[r] = ffma2(wA_o, q.x, aO[r]); aO[r] = ffma2(wB_o, q.y, aO[r]);
                }
            }

#pragma unroll
            for (int r = 0; r < R; ++r)
                epi(aI[r], aF[r], aG[r], aO[r], h[r], c[r]);

            // publish h for next step into the other parity buffer
#pragma unroll
            for (int r = 0; r < R; ++r)
                hbuf[wib][p ^ 1][r][lane] = h[r];
            __syncwarp();
            p ^= 1;
        }
    }

#pragma unroll
    for (int r = 0; r < R; ++r)
        out[(b0 + r) * HH + lane] = h[r];
}

__global__ void __launch_bounds__(32 * WPB)
lstm_balanced(const float* __restrict__ x,
              const float* __restrict__ W_ih,
              const float* __restrict__ W_hh,
              const float* __restrict__ b_ih,
              const float* __restrict__ b_hh,
              float* __restrict__ out)
{
    // [warp][parity][row][hidden] - 128B row stride, 16B aligned for LDS.128
    __shared__ __align__(16) float hbuf[WPB][2][RPWMAX][HH];
    // [warp][row][step][4]  (x0,x1,x2,0) -> one LDS.128 per row-step
    __shared__ __align__(16) float xbuf[WPB][RPWMAX][32][4];

    const int lane = threadIdx.x & 31;
    const int wib  = threadIdx.x >> 5;
    const int gw   = blockIdx.x * WPB + wib;

    // Branch is uniform per block (block 0..135 all-4row, 136..295 all-3row).
    if (gw < NWARP4) {
        const int b0 = gw * 4;                      // rows [0, 2176)
        lstm_body<4>(lane, wib, b0, x, W_ih, W_hh, b_ih, b_hh, out, hbuf, xbuf);
    } else {
        const int b0 = ROWS4 + (gw - NWARP4) * 3;   // rows [2176, 4096)
        lstm_body<3>(lane, wib, b0, x, W_ih, W_hh, b_ih, b_hh, out, hbuf, xbuf);
    }
}

extern "C" void kernel_launch(void* const* d_in, const int* in_sizes, int n_in,
                              void* d_out, int out_size) {
    const float* x    = (const float*)d_in[0];
    const float* W_ih = (const float*)d_in[1];
    const float* W_hh = (const float*)d_in[2];
    const float* b_ih = (const float*)d_in[3];
    const float* b_hh = (const float*)d_in[4];
    float* out = (float*)d_out;

    // 296 blocks x 4 warps = 1184 warps = exactly 2 blocks per SM, one wave.
    dim3 block(32 * WPB);
    dim3 grid(GRID);
    lstm_balanced<<<grid, block>>>(x, W_ih, W_hh, b_ih, b_hh, out);
}

// round 12
// speedup vs baseline: 1.3406x; 1.0848x over previous
#include <cuda_runtime.h>
#include <cuda_bf16.h>
#include <cstdint>

// LSTM: B=4096, T=2048, I=3, H=32.  out = h_final [B, H] fp32.
// Inputs: x [B,T,I], W_ih [4H,I], W_hh [4H,H], b_ih [4H], b_hh [4H]
//
// R11-winning structure (balanced single wave): 296 blocks x 4 warps = 1184
// warps = exactly 2 blocks/SM. Blocks 0..135: 4 rows/warp (2176 rows);
// blocks 136..295: 3 rows/warp (1920 rows). Max SMSP load 7 rows.
// W_hh register-resident packed for fma.rn.f32x2 (shared across rows);
// h via per-warp smem parity buffer read as LDS.128 pre-packed pairs;
// x via padded smem; pipelined gmem staging.
//
// R12 change (isolated): activations via hardware tanh.approx.f32 (1 MUFU)
// instead of ex2/rcp compositions. sigmoid(x) = 0.5 + 0.5*tanh(x/2).
// Cuts epilogue from 21 fma + 10 MUFU (chain ~100cyc) to 13 fma + 5 MUFU
// (chain ~40cyc) per row-step. Precision: MUFU tanh ~1e-4 rms; forget-gate
// decay keeps c-drift bounded (no random walk) -> predicted rel_err 1e-4..7e-4.

#define BB 4096
#define TT 2048
#define II 3
#define HH 32
#define RPWMAX 4
#define WPB 4            // warps per block
#define NBLK4 136        // blocks whose warps take 4 rows
#define NWARP4 (NBLK4 * WPB)       // 544
#define ROWS4 (NWARP4 * 4)         // 2176
#define GRID (148 * 2)             // 296 blocks = 1184 warps, 2 blocks/SM

typedef unsigned long long u64;

__device__ __forceinline__ u64 pack2(float x, float y) {
    u64 r; asm("mov.b64 %0, {%1, %2};" : "=l"(r) : "f"(x), "f"(y)); return r;
}
__device__ __forceinline__ void unpack2(u64 v, float& a, float& b) {
    asm("mov.b64 {%0, %1}, %2;" : "=f"(a), "=f"(b) : "l"(v));
}
// Blackwell packed dual-fp32 fma: d.lo = a.lo*b.lo + c.lo ; d.hi = a.hi*b.hi + c.hi
__device__ __forceinline__ u64 ffma2(u64 a, u64 b, u64 c) {
    u64 d; asm("fma.rn.f32x2 %0, %1, %2, %3;" : "=l"(d) : "l"(a), "l"(b), "l"(c));
    return d;
}

// hardware tanh (sm_75+): single MUFU op, max abs err ~4.9e-4, rms ~1e-4
__device__ __forceinline__ float tanha(float x) {
    float r; asm("tanh.approx.f32 %0, %1;" : "=f"(r) : "f"(x)); return r;
}
// sigmoid via tanh identity: sigm(x) = 0.5 + 0.5*tanh(0.5x)
__device__ __forceinline__ float sigm(float x) {
    return fmaf(0.5f, tanha(0.5f * x), 0.5f);
}

// per-row LSTM epilogue: gates -> (h, c) update
__device__ __forceinline__ void epi(u64 aI, u64 aF, u64 aG, u64 aO,
                                    float& h, float& c) {
    float l0, m0, l1, m1, l2, m2, l3, m3;
    unpack2(aI, l0, m0); unpack2(aF, l1, m1);
    unpack2(aG, l2, m2); unpack2(aO, l3, m3);
    // g first: it heads the longest serial chain (g -> c -> tanh(c) -> h)
    float gg = l2 + m2, gi = l0 + m0, gf = l1 + m1, go = l3 + m3;
    float gv = tanha(gg);
    float ig = sigm(gi), fg = sigm(gf), og = sigm(go);
    c = fmaf(fg, c, ig * gv);
    h = og * tanha(c);
}

// The full per-warp LSTM over R batch rows. R is compile-time (3 or 4).
template<int R>
__device__ __forceinline__ void lstm_body(
    int lane, int wib, int b0,
    const float* __restrict__ x,
    const float* __restrict__ W_ih,
    const float* __restrict__ W_hh,
    const float* __restrict__ b_ih,
    const float* __restrict__ b_hh,
    float* __restrict__ out,
    float (&hbuf)[WPB][2][RPWMAX][HH],
    float (&xbuf)[WPB][RPWMAX][32][4])
{
    const int gi_ = lane, gf_ = lane + 32, gg_ = lane + 64, go_ = lane + 96;

    // ---- W_hh rows into registers, packed along k in pairs (shared by rows) ----
    u64 WI[16], WF[16], WG[16], WO[16];
    {
        const float2* wi = reinterpret_cast<const float2*>(W_hh + gi_ * HH);
        const float2* wf = reinterpret_cast<const float2*>(W_hh + gf_ * HH);
        const float2* wg = reinterpret_cast<const float2*>(W_hh + gg_ * HH);
        const float2* wo = reinterpret_cast<const float2*>(W_hh + go_ * HH);
#pragma unroll
        for (int k = 0; k < 16; ++k) {
            float2 a;
            a = wi[k]; WI[k] = pack2(a.x, a.y);
            a = wf[k]; WF[k] = pack2(a.x, a.y);
            a = wg[k]; WG[k] = pack2(a.x, a.y);
            a = wo[k]; WO[k] = pack2(a.x, a.y);
        }
    }

    // ---- W_ih rows (I=3): packed (w0,w1) and (w2,0) per gate ----
    const u64 XI0 = pack2(W_ih[gi_*II + 0], W_ih[gi_*II + 1]);
    const u64 XI2 = pack2(W_ih[gi_*II + 2], 0.0f);
    const u64 XF0 = pack2(W_ih[gf_*II + 0], W_ih[gf_*II + 1]);
    const u64 XF2 = pack2(W_ih[gf_*II + 2], 0.0f);
    const u64 XG0 = pack2(W_ih[gg_*II + 0], W_ih[gg_*II + 1]);
    const u64 XG2 = pack2(W_ih[gg_*II + 2], 0.0f);
    const u64 XO0 = pack2(W_ih[go_*II + 0], W_ih[go_*II + 1]);
    const u64 XO2 = pack2(W_ih[go_*II + 2], 0.0f);

    // ---- biases (b_ih + b_hh) folded into accumulator init (lo half) ----
    const u64 BI = pack2(b_ih[gi_] + b_hh[gi_], 0.0f);
    const u64 BF = pack2(b_ih[gf_] + b_hh[gf_], 0.0f);
    const u64 BG = pack2(b_ih[gg_] + b_hh[gg_], 0.0f);
    const u64 BO = pack2(b_ih[go_] + b_hh[go_], 0.0f);

    const float* xp[R];
#pragma unroll
    for (int r = 0; r < R; ++r)
        xp[r] = x + (size_t)(b0 + r) * (TT * II);

    float h[R], c[R];
#pragma unroll
    for (int r = 0; r < R; ++r) { h[r] = 0.0f; c[r] = 0.0f; }

    // init h parity-0 buffer with h_{-1} = 0; zero xbuf pad words once
#pragma unroll
    for (int r = 0; r < R; ++r) {
        hbuf[wib][0][r][lane] = 0.0f;
        xbuf[wib][r][lane][3] = 0.0f;
    }

    // ---- prefetch chunk 0 x into registers (coalesced) ----
    float pA[R], pB[R], pC[R];
#pragma unroll
    for (int r = 0; r < R; ++r) {
        pA[r] = xp[r][lane];
        pB[r] = xp[r][32 + lane];
        pC[r] = xp[r][64 + lane];
    }

    // staging remap: flat index j in [0,96) -> (step j/3, comp j%3)
    const int tA = lane / 3,        cA = lane - 3 * tA;
    const int tB = (32 + lane) / 3, cB = (32 + lane) - 3 * tB;
    const int tC = (64 + lane) / 3, cC = (64 + lane) - 3 * tC;

    int p = 0;
    __syncwarp();

    for (int t0 = 0; t0 < TT; t0 += 32) {
        // stage current chunk's x into smem (remapped to 4-float stride)
#pragma unroll
        for (int r = 0; r < R; ++r) {
            float* xr = &xbuf[wib][r][0][0];
            xr[4*tA + cA] = pA[r];
            xr[4*tB + cB] = pB[r];
            xr[4*tC + cC] = pC[r];
        }

        // prefetch next chunk (hides DRAM latency under 32 inner steps)
        if (t0 + 32 < TT) {
#pragma unroll
            for (int r = 0; r < R; ++r) {
                const float* xn = xp[r] + (t0 + 32) * II;
                pA[r] = xn[lane];
                pB[r] = xn[32 + lane];
                pC[r] = xn[64 + lane];
            }
        }
        __syncwarp();

#pragma unroll 2
        for (int s = 0; s < 32; ++s) {
            u64 aI[R], aF[R], aG[R], aO[R];

            // x: one LDS.128 per row; .x = packed (x0,x1), .y = (x2, 0)
#pragma unroll
            for (int r = 0; r < R; ++r) {
                ulonglong2 xv = *reinterpret_cast<const ulonglong2*>(&xbuf[wib][r][s][0]);
                aI[r] = ffma2(XI0, xv.x, BI); aI[r] = ffma2(XI2, xv.y, aI[r]);
                aF[r] = ffma2(XF0, xv.x, BF); aF[r] = ffma2(XF2, xv.y, aF[r]);
                aG[r] = ffma2(XG0, xv.x, BG); aG[r] = ffma2(XG2, xv.y, aG[r]);
                aO[r] = ffma2(XO0, xv.x, BO); aO[r] = ffma2(XO2, xv.y, aO[r]);
            }

            // recurrent matvec: 8 LDS.128 per row, bits are pre-packed f32x2 pairs
#pragma unroll
            for (int k = 0; k < 8; ++k) {
                const u64 wA_i = WI[2*k], wB_i = WI[2*k+1];
                const u64 wA_f = WF[2*k], wB_f = WF[2*k+1];
                const u64 wA_g = WG[2*k], wB_g = WG[2*k+1];
                const u64 wA_o = WO[2*k], wB_o = WO[2*k+1];
#pragma unroll
                for (int r = 0; r < R; ++r) {
                    ulonglong2 q = *reinterpret_cast<const ulonglong2*>(
                        &hbuf[wib][p][r][0] + 4 * k);
                    aI[r] = ffma2(wA_i, q.x, aI[r]); aI[r] = ffma2(wB_i, q.y, aI[r]);
                    aF[r] = ffma2(wA_f, q.x, aF[r]); aF[r] = ffma2(wB_f, q.y, aF[r]);
                    aG[r] = ffma2(wA_g, q.x, aG[r]); aG[r] = ffma2(wB_g, q.y, aG[r]);
                    aO[r] = ffma2(wA_o, q.x, aO[r]); aO[r] = ffma2(wB_o, q.y, aO[r]);
                }
            }

#pragma unroll
            for (int r = 0; r < R; ++r)
                epi(aI[r], aF[r], aG[r], aO[r], h[r], c[r]);

            // publish h for next step into the other parity buffer
#pragma unroll
            for (int r = 0; r < R; ++r)
                hbuf[wib][p ^ 1][r][lane] = h[r];
            __syncwarp();
            p ^= 1;
        }
    }

#pragma unroll
    for (int r = 0; r < R; ++r)
        out[(b0 + r) * HH + lane] = h[r];
}

__global__ void __launch_bounds__(32 * WPB)
lstm_balanced(const float* __restrict__ x,
              const float* __restrict__ W_ih,
              const float* __restrict__ W_hh,
              const float* __restrict__ b_ih,
              const float* __restrict__ b_hh,
              float* __restrict__ out)
{
    // [warp][parity][row][hidden] - 128B row stride, 16B aligned for LDS.128
    __shared__ __align__(16) float hbuf[WPB][2][RPWMAX][HH];
    // [warp][row][step][4]  (x0,x1,x2,0) -> one LDS.128 per row-step
    __shared__ __align__(16) float xbuf[WPB][RPWMAX][32][4];

    const int lane = threadIdx.x & 31;
    const int wib  = threadIdx.x >> 5;
    const int gw   = blockIdx.x * WPB + wib;

    // Branch is uniform per block (block 0..135 all-4row, 136..295 all-3row).
    if (gw < NWARP4) {
        const int b0 = gw * 4;                      // rows [0, 2176)
        lstm_body<4>(lane, wib, b0, x, W_ih, W_hh, b_ih, b_hh, out, hbuf, xbuf);
    } else {
        const int b0 = ROWS4 + (gw - NWARP4) * 3;   // rows [2176, 4096)
        lstm_body<3>(lane, wib, b0, x, W_ih, W_hh, b_ih, b_hh, out, hbuf, xbuf);
    }
}

extern "C" void kernel_launch(void* const* d_in, const int* in_sizes, int n_in,
                              void* d_out, int out_size) {
    const float* x    = (const float*)d_in[0];
    const float* W_ih = (const float*)d_in[1];
    const float* W_hh = (const float*)d_in[2];
    const float* b_ih = (const float*)d_in[3];
    const float* b_hh = (const float*)d_in[4];
    float* out = (float*)d_out;

    // 296 blocks x 4 warps = 1184 warps = exactly 2 blocks per SM, one wave.
    dim3 block(32 * WPB);
    dim3 grid(GRID);
    lstm_balanced<<<grid, block>>>(x, W_ih, W_hh, b_ih, b_hh, out);
}